// round 9
// baseline (speedup 1.0000x reference)
#include <cuda_runtime.h>
#include <math.h>

#define HH  192
#define NPX 36864
#define NB  4
#define NCH 192
#define QW  96
#define NQ  9216          // 96*96 quadrant pixels
#define NT  2304          // stats tiles: 4 batches * 576 pixel-blocks
#define NTILE 136         // upper-triangular 4x4 tiles of 16x16 tile grid
#define GPW 2240          // 136*16 Gram entries + 64 S entries

__device__ float2 d_Wf[HH*HH];
__device__ float2 d_Wb[HH*HH];
__device__ float2 d_Y[12][NPX];
__device__ float2 d_F[12][NPX];
__device__ float  d_h2q[NB*NQ*NCH];
__device__ float  d_gpart[NT][GPW];
__device__ double d_gmid[36][GPW];
__device__ double d_Gd[NTILE*16];
__device__ double d_Sd[64];
__device__ float  d_bnA[NCH], d_bnB[NCH];
__device__ float2 d_A[NQ];
__device__ float2 d_T[64][QW*HH];
__device__ float  d_xf[64*NPX];
__device__ float4 d_soiA[576];
__device__ float2 d_soiB[576];
__device__ int    d_band[192*2];
__device__ float  d_pix[3][NPX];

// ---- FMA-poly transcendentals ----
__device__ __forceinline__ float fexp(float x) {
    if (!(x > -87.33654f)) return 0.0f;
    float y = x * 1.4426950408889634f;
    float n = rintf(y);
    float f = y - n;
    float p = 1.5403530e-4f;
    p = fmaf(p, f, 1.3333558e-3f);
    p = fmaf(p, f, 9.6181291e-3f);
    p = fmaf(p, f, 5.5504109e-2f);
    p = fmaf(p, f, 2.4022651e-1f);
    p = fmaf(p, f, 6.9314718e-1f);
    p = fmaf(p, f, 1.0f);
    return __int_as_float(((int)n + 127) << 23) * p;
}
__device__ __forceinline__ float fcos(float x) {   // |x| < ~6
    float qf = rintf(x * 0.6366197723675814f);
    int   q  = (int)qf;
    float t  = fmaf(qf, -1.5707963705062866f, x);
    t = fmaf(qf, 4.3711388e-8f, t);
    float s = t * t;
    float c = fmaf(s, fmaf(s, fmaf(s, 2.4433157e-5f, -1.3887316e-3f), 4.1666646e-2f), -0.5f);
    c = fmaf(c, s, 1.0f);
    float sn = t * fmaf(s, fmaf(s, fmaf(s, -1.9515296e-4f, 8.3321609e-3f), -1.6666655e-1f), 1.0f);
    int qm = q & 3;
    return (qm == 0) ? c : (qm == 1) ? -sn : (qm == 2) ? -c : sn;
}

__device__ __forceinline__ float2 cmul(float2 a, float2 b) {
    return make_float2(fmaf(a.x, b.x, -a.y * b.y), fmaf(a.x, b.y, a.y * b.x));
}

// ---- fused init: DFT matrices + pixel grid + gabor params + bands ----
__global__ void k_init(const float* freq, const float* theta, const float* sigma,
                       const float* f0, const float* theta0, const float* fbs) {
    int idx = blockIdx.x * blockDim.x + threadIdx.x;
    if (idx >= NPX) return;
    {   // DFT twiddle tables
        int k = idx / HH, n = idx % HH;
        int m = (k * n) % HH;
        float s, c;
        sincospif((float)m / 96.0f, &s, &c);
        d_Wf[idx] = make_float2(c, -s);
        d_Wb[idx] = make_float2(c * (1.0f / 192.0f), s * (1.0f / 192.0f));
    }
    {   // pixel grid (shifted coords at unshifted index)
        int u = idx / HH, v = idx % HH;
        int hs = (u >= 96) ? u - 96 : u + 96;
        int ws = (v >= 96) ? v - 96 : v + 96;
        float yy = -1.0f + hs * (2.0f / 191.0f);
        float xx = -1.0f + ws * (2.0f / 191.0f);
        float r  = sqrtf(xx * xx + yy * yy + 1e-6f);
        d_pix[0][idx] = logf(r);
        d_pix[1][idx] = atan2f(yy, xx);
        d_pix[2][idx] = r;
    }
    if (idx < 576) {
        float sg = sigma[idx], f0v = f0[idx], t0 = theta0[idx];
        float lf0 = logf(f0v);
        float dl  = logf(sg) - lf0;
        d_soiA[idx] = make_float4(lf0, 0.5f / (dl * dl), theta[idx], 0.5f / (t0 * t0));
        d_soiB[idx] = make_float2(freq[idx], 1.0f / (6.283185307179586f * sg * sg));
    }
    if (idx < 192) {
        d_band[idx * 2 + 0] = (int)floorf((fbs[idx * 2 + 0] + 1.0f) * 0.5f * 192.0f);
        d_band[idx * 2 + 1] = (int)floorf((fbs[idx * 2 + 1] + 1.0f) * 0.5f * 192.0f);
    }
}

// ---- forward DFT rows: rotator twiddles, no per-iter global loads ----
__global__ __launch_bounds__(192) void k_fwd_rows(const float* x) {
    int im = blockIdx.x, h0 = blockIdx.y * 8, tid = threadIdx.x;
    __shared__ float xs[8][HH];
    const float* xim = x + im * NPX;
    for (int j = tid; j < 8 * HH; j += 192)
        xs[j / HH][j % HH] = xim[(h0 + j / HH) * HH + (j % HH)];
    __syncthreads();
    float sn, cs;
    sincospif(-(float)tid / 96.0f, &sn, &cs);
    float2 step = make_float2(cs, sn);
    float2 cur  = make_float2(1.0f, 0.0f);
    float ar[8], ai[8];
    #pragma unroll
    for (int r = 0; r < 8; r++) { ar[r] = 0.0f; ai[r] = 0.0f; }
    #pragma unroll 4
    for (int w = 0; w < HH; w++) {
        float2 W = cur;
        #pragma unroll
        for (int r = 0; r < 8; r++) {
            float xv = xs[r][w];
            ar[r] = fmaf(xv, W.x, ar[r]);
            ai[r] = fmaf(xv, W.y, ai[r]);
        }
        cur = cmul(cur, step);
    }
    #pragma unroll
    for (int r = 0; r < 8; r++)
        d_Y[im][(h0 + r) * HH + tid] = make_float2(ar[r], ai[r]);
}

// ---- forward DFT cols: chunked smem staging of Y ----
__global__ __launch_bounds__(192) void k_fwd_cols() {
    int im = blockIdx.x, u0 = blockIdx.y * 8, tid = threadIdx.x;
    __shared__ float2 wt[8][HH];
    __shared__ float2 ys[16][HH];
    for (int j = tid; j < 8 * HH; j += 192)
        wt[j / HH][j % HH] = d_Wf[(u0 + j / HH) * HH + (j % HH)];
    float fr[8], fi[8];
    #pragma unroll
    for (int r = 0; r < 8; r++) { fr[r] = 0.0f; fi[r] = 0.0f; }
    for (int ch = 0; ch < 12; ch++) {
        __syncthreads();
        #pragma unroll
        for (int i = 0; i < 16; i++)
            ys[i][tid] = d_Y[im][(ch * 16 + i) * HH + tid];
        __syncthreads();
        #pragma unroll
        for (int i = 0; i < 16; i++) {
            float2 y = ys[i][tid];
            #pragma unroll
            for (int r = 0; r < 8; r++) {
                float2 w = wt[r][ch * 16 + i];
                fr[r] = fmaf(w.x, y.x, fmaf(-w.y, y.y, fr[r]));
                fi[r] = fmaf(w.x, y.y, fmaf( w.y, y.x, fi[r]));
            }
        }
    }
    #pragma unroll
    for (int r = 0; r < 8; r++)
        d_F[im][(u0 + r) * HH + tid] = make_float2(fr[r], fi[r]);
}

// ---- h1 helper ----
__device__ __forceinline__ float h1_val(int b, int px, float w1a, float w1b, float w1c, float b1v) {
    float mg[3];
    #pragma unroll
    for (int c = 0; c < 3; c++) {
        int ip = (c == 0) ? 2 : (c - 1);      // channel fftshift perm
        float2 F = d_F[b * 3 + ip][px];
        mg[c] = sqrtf(F.x * F.x + F.y * F.y);
    }
    return fmaxf(fmaf(w1a, mg[0], fmaf(w1b, mg[1], fmaf(w1c, mg[2], b1v))), 0.0f);
}

// ---- attention stats: S = sum h1, G = sum h1 h1^T (upper 4x4 tiles) ----
__global__ __launch_bounds__(192) void k_attn_stats(const float* w1, const float* b1) {
    int b = blockIdx.x, py = blockIdx.y, px0 = py * 64, tid = threadIdx.x;
    __shared__ float h1s[64][65];
    int hid = tid & 63, grp = tid >> 6;
    float w1a = w1[hid * 3], w1b = w1[hid * 3 + 1], w1c = w1[hid * 3 + 2], b1v = b1[hid];
    for (int q = grp; q < 16; q += 3) {
        #pragma unroll
        for (int pp = 0; pp < 4; pp++)
            h1s[hid][q * 4 + pp] = h1_val(b, px0 + q * 4 + pp, w1a, w1b, w1c, b1v);
    }
    __syncthreads();
    int blk = b * 576 + py;
    if (tid < 64) {
        float s = 0.0f;
        #pragma unroll 8
        for (int p = 0; p < 64; p++) s += h1s[tid][p];
        d_gpart[blk][NTILE * 16 + tid] = s;
    }
    if (tid < NTILE) {
        int J = 0, rem = tid;
        while (rem >= 16 - J) { rem -= 16 - J; J++; }
        int K = J + rem;
        float acc[4][4];
        #pragma unroll
        for (int a = 0; a < 4; a++)
            #pragma unroll
            for (int c = 0; c < 4; c++) acc[a][c] = 0.0f;
        #pragma unroll 2
        for (int p = 0; p < 64; p++) {
            float ra[4], rb[4];
            #pragma unroll
            for (int a = 0; a < 4; a++) ra[a] = h1s[J * 4 + a][p];
            #pragma unroll
            for (int c = 0; c < 4; c++) rb[c] = h1s[K * 4 + c][p];
            #pragma unroll
            for (int a = 0; a < 4; a++)
                #pragma unroll
                for (int c = 0; c < 4; c++)
                    acc[a][c] = fmaf(ra[a], rb[c], acc[a][c]);
        }
        #pragma unroll
        for (int a = 0; a < 4; a++)
            #pragma unroll
            for (int c = 0; c < 4; c++)
                d_gpart[blk][tid * 16 + a * 4 + c] = acc[a][c];
    }
}

// ---- attention h2 on quadrant pixels only ----
__global__ __launch_bounds__(192) void k_attn_h2(const float* w1, const float* b1,
                                                 const float* w2, const float* b2) {
    int b = blockIdx.x, q0 = blockIdx.y * 64, tid = threadIdx.x;
    __shared__ float h1s[64][64];
    int hid = tid & 63, grp = tid >> 6;
    float w1a = w1[hid * 3], w1b = w1[hid * 3 + 1], w1c = w1[hid * 3 + 2], b1v = b1[hid];
    for (int g = grp; g < 16; g += 3) {
        float h[4];
        #pragma unroll
        for (int pp = 0; pp < 4; pp++) {
            int q = q0 + g * 4 + pp;
            int px = (q / QW) * HH + (q % QW);
            h[pp] = h1_val(b, px, w1a, w1b, w1c, b1v);
        }
        *(float4*)&h1s[hid][g * 4] = make_float4(h[0], h[1], h[2], h[3]);
    }
    float w2row[64];
    #pragma unroll
    for (int j = 0; j < 64; j++) w2row[j] = w2[tid * 64 + j];
    float bias2 = b2[tid];
    __syncthreads();
    for (int g = 0; g < 16; g++) {
        float a0 = bias2, a1 = bias2, a2 = bias2, a3 = bias2;
        #pragma unroll
        for (int j = 0; j < 64; j++) {
            float4 h = *(const float4*)&h1s[j][g * 4];
            float wv = w2row[j];
            a0 = fmaf(wv, h.x, a0); a1 = fmaf(wv, h.y, a1);
            a2 = fmaf(wv, h.z, a2); a3 = fmaf(wv, h.w, a3);
        }
        long base = ((long)b * NQ + q0 + g * 4) * NCH + tid;
        d_h2q[base          ] = a0;
        d_h2q[base + NCH    ] = a1;
        d_h2q[base + 2 * NCH] = a2;
        d_h2q[base + 3 * NCH] = a3;
    }
}

// ---- Gram/S reduction, two deterministic stages ----
__global__ __launch_bounds__(256) void k_gred1() {
    int m = blockIdx.x;
    for (int e = threadIdx.x; e < GPW; e += 256) {
        double s = 0.0;
        for (int blk = m * 64; blk < m * 64 + 64; blk++)
            s += (double)d_gpart[blk][e];
        d_gmid[m][e] = s;
    }
}
__global__ __launch_bounds__(256) void k_gred2() {
    for (int e = threadIdx.x; e < GPW; e += 256) {
        double s = 0.0;
        for (int m = 0; m < 36; m++) s += d_gmid[m][e];
        if (e < NTILE * 16) d_Gd[e] = s;
        else d_Sd[e - NTILE * 16] = s;
    }
}

// ---- BN finalize via quadratic form ----
__global__ __launch_bounds__(64) void k_bnfin(const float* w2, const float* b2,
                                              const float* bnw, const float* bnb) {
    int c = blockIdx.x, j = threadIdx.x;
    __shared__ float w2s[64];
    __shared__ double sh1[64], sh2[64];
    w2s[j] = w2[c * 64 + j];
    __syncthreads();
    double wj = (double)w2s[j];
    double rowsum = 0.0;
    for (int k = 0; k < 64; k++) {
        int J = j >> 2, K = k >> 2, rj = j & 3, rk = k & 3;
        int off;
        if (J <= K) off = (J * 16 - (J * (J - 1)) / 2 + (K - J)) * 16 + rj * 4 + rk;
        else        off = (K * 16 - (K * (K - 1)) / 2 + (J - K)) * 16 + rk * 4 + rj;
        rowsum += d_Gd[off] * (double)w2s[k];
    }
    sh1[j] = wj * rowsum;
    sh2[j] = wj * d_Sd[j];
    __syncthreads();
    if (j == 0) {
        double quad = 0.0, ws = 0.0;
        for (int k = 0; k < 64; k++) { quad += sh1[k]; ws += sh2[k]; }
        double N   = (double)((long)NB * NPX);
        double b2c = (double)b2[c];
        double mu  = (ws + N * b2c) / N;
        double msq = (quad + 2.0 * b2c * ws + N * b2c * b2c) / N;
        double var = msq - mu * mu;
        float inv  = (float)(1.0 / sqrt(var + 1e-5));
        float A    = inv * bnw[c];
        d_bnA[c] = A;
        d_bnB[c] = bnb[c] - (float)mu * A;
    }
}

// ---- fused BN + softmax + gabor + A_tot (quadrant only) ----
__global__ __launch_bounds__(192) void k_atot() {
    int q = blockIdx.x, tid = threadIdx.x;
    int u = q / QW, v = q % QW;
    int px = u * HH + v;
    __shared__ float2 xsh[4][3];
    __shared__ float4 red4[6];
    __shared__ float2 red2[6];
    __shared__ float  pixsh[3];
    float A = d_bnA[tid], Bb = d_bnB[tid];
    float e0, e1, e2, e3;
    {
        long base = (long)q * NCH + tid;
        e0 = fexp(fmaf(d_h2q[base               ], A, Bb));
        e1 = fexp(fmaf(d_h2q[base + (long)NQ*NCH], A, Bb));
        e2 = fexp(fmaf(d_h2q[base + 2l*NQ*NCH   ], A, Bb));
        e3 = fexp(fmaf(d_h2q[base + 3l*NQ*NCH   ], A, Bb));
    }
    if (tid < 12) {
        int b = tid / 3, i = tid % 3;
        int ip = (i == 0) ? 2 : (i - 1);
        xsh[b][i] = d_F[b * 3 + ip][px];
    }
    if (tid == 12) { pixsh[0] = d_pix[0][px]; pixsh[1] = d_pix[1][px]; pixsh[2] = d_pix[2][px]; }
    float s0 = e0, s1 = e1, s2 = e2, s3 = e3;
    #pragma unroll
    for (int o = 16; o > 0; o >>= 1) {
        s0 += __shfl_xor_sync(0xffffffffu, s0, o);
        s1 += __shfl_xor_sync(0xffffffffu, s1, o);
        s2 += __shfl_xor_sync(0xffffffffu, s2, o);
        s3 += __shfl_xor_sync(0xffffffffu, s3, o);
    }
    __syncthreads();
    if ((tid & 31) == 0) red4[tid >> 5] = make_float4(s0, s1, s2, s3);
    __syncthreads();
    float4 S = red4[0];
    #pragma unroll
    for (int wI = 1; wI < 6; wI++) {
        float4 t = red4[wI];
        S.x += t.x; S.y += t.y; S.z += t.z; S.w += t.w;
    }
    float at0 = e0 / S.x, at1 = e1 / S.y, at2 = e2 / S.z, at3 = e3 / S.w;
    float L = pixsh[0], phi = pixsh[1], r = pixsh[2];
    float accr = 0.0f, acci = 0.0f;
    #pragma unroll
    for (int i = 0; i < 3; i++) {
        float ar = at0 * xsh[0][i].x + at1 * xsh[1][i].x + at2 * xsh[2][i].x + at3 * xsh[3][i].x;
        float ai = at0 * xsh[0][i].y + at1 * xsh[1][i].y + at2 * xsh[2][i].y + at3 * xsh[3][i].y;
        float4 pa = d_soiA[tid * 3 + i];
        float2 pb = d_soiB[tid * 3 + i];
        float dl = L - pa.x;
        float dp = phi - pa.z;
        float g = fexp(-(dl * dl) * pa.y - (dp * dp) * pa.w) * fcos(pb.x * r) * pb.y;
        accr = fmaf(g, ar, accr);
        acci = fmaf(g, ai, acci);
    }
    #pragma unroll
    for (int o = 16; o > 0; o >>= 1) {
        accr += __shfl_xor_sync(0xffffffffu, accr, o);
        acci += __shfl_xor_sync(0xffffffffu, acci, o);
    }
    __syncthreads();
    if ((tid & 31) == 0) red2[tid >> 5] = make_float2(accr, acci);
    __syncthreads();
    if (tid == 0) {
        float2 t = red2[0];
        #pragma unroll
        for (int wI = 1; wI < 6; wI++) { t.x += red2[wI].x; t.y += red2[wI].y; }
        d_A[q] = t;
    }
}

// ---- inverse DFT rows: rotator twiddles, quadrant-restricted, mask fused ----
__global__ __launch_bounds__(192) void k_inv_rows() {
    int o = blockIdx.x, u0 = blockIdx.y * 8, tid = threadIdx.x;
    int os = (o + 32) & 63;
    int lo0 = d_band[(os * 3 + 0) * 2] - 96, hi0 = d_band[(os * 3 + 0) * 2 + 1] - 96;
    int lo1 = d_band[(os * 3 + 1) * 2] - 96, hi1 = d_band[(os * 3 + 1) * 2 + 1] - 96;
    int lo2 = d_band[(os * 3 + 2) * 2] - 96, hi2 = d_band[(os * 3 + 2) * 2 + 1] - 96;
    __shared__ float2 qs[8][QW];
    for (int j = tid; j < 8 * QW; j += 192) {
        int r = j / QW, v = j % QW;
        int u = u0 + r;
        bool a0 = (u >= lo0) && (u < hi0), b0 = (v >= lo0) && (v < hi0);
        bool a1 = (u >= lo1) && (u < hi1), b1 = (v >= lo1) && (v < hi1);
        bool a2 = (u >= lo2) && (u < hi2), b2 = (v >= lo2) && (v < hi2);
        float m = (float)((a0 & b0) + (a1 & b1) + (a2 & b2));
        float2 a = d_A[u * QW + v];
        qs[r][v] = make_float2(a.x * m, a.y * m);
    }
    __syncthreads();
    float sn, cs;
    sincospif((float)tid / 96.0f, &sn, &cs);
    float2 step = make_float2(cs, sn);
    float2 cur  = make_float2(1.0f, 0.0f);
    float tr[8], ti[8];
    #pragma unroll
    for (int r = 0; r < 8; r++) { tr[r] = 0.0f; ti[r] = 0.0f; }
    #pragma unroll 4
    for (int v = 0; v < QW; v++) {
        float2 w = cur;
        #pragma unroll
        for (int r = 0; r < 8; r++) {
            float2 qv = qs[r][v];
            tr[r] = fmaf(qv.x, w.x, fmaf(-qv.y, w.y, tr[r]));
            ti[r] = fmaf(qv.x, w.y, fmaf( qv.y, w.x, ti[r]));
        }
        cur = cmul(cur, step);
    }
    const float sc = 1.0f / 192.0f;
    #pragma unroll
    for (int r = 0; r < 8; r++)
        d_T[o][(u0 + r) * HH + tid] = make_float2(tr[r] * sc, ti[r] * sc);
}

// ---- inverse DFT cols (real part): chunked smem staging of T ----
__global__ __launch_bounds__(192) void k_inv_cols() {
    int o = blockIdx.x, s0 = blockIdx.y * 8, tid = threadIdx.x;
    __shared__ float2 wt[8][QW];
    __shared__ float2 ts[16][HH];
    for (int j = tid; j < 8 * QW; j += 192) {
        int r = j / QW, u = j % QW;
        wt[r][u] = d_Wb[(s0 + r) * HH + u];
    }
    float acc[8];
    #pragma unroll
    for (int r = 0; r < 8; r++) acc[r] = 0.0f;
    for (int ch = 0; ch < 6; ch++) {
        __syncthreads();
        #pragma unroll
        for (int i = 0; i < 16; i++)
            ts[i][tid] = d_T[o][(ch * 16 + i) * HH + tid];
        __syncthreads();
        #pragma unroll
        for (int i = 0; i < 16; i++) {
            float2 t = ts[i][tid];
            #pragma unroll
            for (int r = 0; r < 8; r++) {
                float2 w = wt[r][ch * 16 + i];
                acc[r] = fmaf(w.x, t.x, fmaf(-w.y, t.y, acc[r]));
            }
        }
    }
    #pragma unroll
    for (int r = 0; r < 8; r++)
        d_xf[o * NPX + (s0 + r) * HH + tid] = acc[r];
}

// ---- 3x3 conv + mixing ----
__global__ __launch_bounds__(256) void k_conv(const float* x, const float* cw,
                                              const float* mp, float* out) {
    int b = blockIdx.z;
    int h0 = blockIdx.y * 16, w0 = blockIdx.x * 16;
    int tx = threadIdx.x, ty = threadIdx.y;
    int t = ty * 16 + tx;
    __shared__ float xt[3][18][18];
    __shared__ float cws[64 * 27];
    for (int j = t; j < 972; j += 256) {
        int i = j / 324, rem = j % 324, hh = rem / 18, ww = rem % 18;
        int gh = h0 - 1 + hh, gw = w0 - 1 + ww;
        xt[i][hh][ww] = (gh >= 0 && gh < HH && gw >= 0 && gw < HH)
                        ? x[(b * 3 + i) * NPX + gh * HH + gw] : 0.0f;
    }
    for (int j = t; j < 1728; j += 256) cws[j] = cw[j];
    __syncthreads();
    float mix = mp[0];
    float win[27];
    #pragma unroll
    for (int i = 0; i < 3; i++)
        #pragma unroll
        for (int kh = 0; kh < 3; kh++)
            #pragma unroll
            for (int kw = 0; kw < 3; kw++)
                win[i * 9 + kh * 3 + kw] = xt[i][ty + kh][tx + kw];
    int pix = (h0 + ty) * HH + (w0 + tx);
    for (int o = 0; o < 64; o++) {
        float acc = 0.0f;
        #pragma unroll
        for (int j = 0; j < 27; j++) acc = fmaf(win[j], cws[o * 27 + j], acc);
        out[((b * 64 + o) * NPX) + pix] = fmaf(mix, d_xf[o * NPX + pix], (1.0f - mix) * acc);
    }
}

extern "C" void kernel_launch(void* const* d_in, const int* in_sizes, int n_in,
                              void* d_out, int out_size) {
    const float* x    = (const float*)d_in[0];
    const float* freq = (const float*)d_in[1];
    const float* thet = (const float*)d_in[2];
    const float* sigm = (const float*)d_in[3];
    const float* f0   = (const float*)d_in[4];
    const float* th0  = (const float*)d_in[5];
    const float* w1   = (const float*)d_in[6];
    const float* b1   = (const float*)d_in[7];
    const float* w2   = (const float*)d_in[8];
    const float* b2   = (const float*)d_in[9];
    const float* bnw  = (const float*)d_in[10];
    const float* bnb  = (const float*)d_in[11];
    const float* mp   = (const float*)d_in[12];
    const float* cw   = (const float*)d_in[13];
    const float* fbs  = (const float*)d_in[14];
    float* out = (float*)d_out;

    k_init<<<144, 256>>>(freq, thet, sigm, f0, th0, fbs);
    k_fwd_rows<<<dim3(12, 24), 192>>>(x);
    k_fwd_cols<<<dim3(12, 24), 192>>>();
    k_attn_stats<<<dim3(4, 576), 192>>>(w1, b1);
    k_attn_h2<<<dim3(4, 144), 192>>>(w1, b1, w2, b2);
    k_gred1<<<36, 256>>>();
    k_gred2<<<1, 256>>>();
    k_bnfin<<<192, 64>>>(w2, b2, bnw, bnb);
    k_atot<<<NQ, 192>>>();
    k_inv_rows<<<dim3(64, 12), 192>>>();
    k_inv_cols<<<dim3(64, 24), 192>>>();
    k_conv<<<dim3(12, 12, 4), dim3(16, 16)>>>(x, cw, mp, out);
}

// round 10
// speedup vs baseline: 1.0011x; 1.0011x over previous
#include <cuda_runtime.h>
#include <math.h>

#define HH  192
#define NPX 36864
#define NB  4
#define NCH 192
#define QW  96
#define NQ  9216          // 96*96 quadrant pixels
#define NT  2304          // stats tiles: 4 batches * 576 pixel-blocks
#define NTILE 136         // upper-triangular 4x4 tiles of 16x16 tile grid
#define GPW 2240          // 136*16 Gram entries + 64 S entries

__device__ float2 d_Wf[HH*HH];
__device__ float2 d_Wb[HH*HH];
__device__ float2 d_Y[12][NPX];
__device__ float2 d_F[12][NPX];
__device__ float  d_h2q[NB*NQ*NCH];
__device__ float  d_gpart[NT][GPW];
__device__ double d_gmid[36][GPW];
__device__ double d_Gd[NTILE*16];
__device__ double d_Sd[64];
__device__ float  d_bnA[NCH], d_bnB[NCH];
__device__ float2 d_A[NQ];
__device__ float2 d_T[64][QW*HH];
__device__ float  d_xf[64*NPX];
__device__ float4 d_soiA[576];
__device__ float2 d_soiB[576];
__device__ int    d_band[192*2];
__device__ float  d_pix[3][NPX];

// ---- FMA-poly transcendentals ----
__device__ __forceinline__ float fexp(float x) {
    if (!(x > -87.33654f)) return 0.0f;
    float y = x * 1.4426950408889634f;
    float n = rintf(y);
    float f = y - n;
    float p = 1.5403530e-4f;
    p = fmaf(p, f, 1.3333558e-3f);
    p = fmaf(p, f, 9.6181291e-3f);
    p = fmaf(p, f, 5.5504109e-2f);
    p = fmaf(p, f, 2.4022651e-1f);
    p = fmaf(p, f, 6.9314718e-1f);
    p = fmaf(p, f, 1.0f);
    return __int_as_float(((int)n + 127) << 23) * p;
}
__device__ __forceinline__ float fcos(float x) {   // |x| < ~6
    float qf = rintf(x * 0.6366197723675814f);
    int   q  = (int)qf;
    float t  = fmaf(qf, -1.5707963705062866f, x);
    t = fmaf(qf, 4.3711388e-8f, t);
    float s = t * t;
    float c = fmaf(s, fmaf(s, fmaf(s, 2.4433157e-5f, -1.3887316e-3f), 4.1666646e-2f), -0.5f);
    c = fmaf(c, s, 1.0f);
    float sn = t * fmaf(s, fmaf(s, fmaf(s, -1.9515296e-4f, 8.3321609e-3f), -1.6666655e-1f), 1.0f);
    int qm = q & 3;
    return (qm == 0) ? c : (qm == 1) ? -sn : (qm == 2) ? -c : sn;
}

// ---- fused init: DFT matrices + pixel grid + gabor params + bands ----
__global__ void k_init(const float* freq, const float* theta, const float* sigma,
                       const float* f0, const float* theta0, const float* fbs) {
    int idx = blockIdx.x * blockDim.x + threadIdx.x;
    if (idx >= NPX) return;
    {
        int k = idx / HH, n = idx % HH;
        int m = (k * n) % HH;
        float s, c;
        sincospif((float)m / 96.0f, &s, &c);
        d_Wf[idx] = make_float2(c, -s);
        d_Wb[idx] = make_float2(c * (1.0f / 192.0f), s * (1.0f / 192.0f));
    }
    {
        int u = idx / HH, v = idx % HH;
        int hs = (u >= 96) ? u - 96 : u + 96;
        int ws = (v >= 96) ? v - 96 : v + 96;
        float yy = -1.0f + hs * (2.0f / 191.0f);
        float xx = -1.0f + ws * (2.0f / 191.0f);
        float r  = sqrtf(xx * xx + yy * yy + 1e-6f);
        d_pix[0][idx] = logf(r);
        d_pix[1][idx] = atan2f(yy, xx);
        d_pix[2][idx] = r;
    }
    if (idx < 576) {
        float sg = sigma[idx], f0v = f0[idx], t0 = theta0[idx];
        float lf0 = logf(f0v);
        float dl  = logf(sg) - lf0;
        d_soiA[idx] = make_float4(lf0, 0.5f / (dl * dl), theta[idx], 0.5f / (t0 * t0));
        d_soiB[idx] = make_float2(freq[idx], 1.0f / (6.283185307179586f * sg * sg));
    }
    if (idx < 192) {
        d_band[idx * 2 + 0] = (int)floorf((fbs[idx * 2 + 0] + 1.0f) * 0.5f * 192.0f);
        d_band[idx * 2 + 1] = (int)floorf((fbs[idx * 2 + 1] + 1.0f) * 0.5f * 192.0f);
    }
}

// ---- forward DFT rows (R8 table version) ----
__global__ __launch_bounds__(192) void k_fwd_rows(const float* x) {
    int im = blockIdx.x, h0 = blockIdx.y * 8, tid = threadIdx.x;
    __shared__ float xs[8][HH];
    const float* xim = x + im * NPX;
    for (int j = tid; j < 8 * HH; j += 192)
        xs[j / HH][j % HH] = xim[(h0 + j / HH) * HH + (j % HH)];
    __syncthreads();
    float ar[8], ai[8];
    #pragma unroll
    for (int r = 0; r < 8; r++) { ar[r] = 0.0f; ai[r] = 0.0f; }
    #pragma unroll 4
    for (int w = 0; w < HH; w++) {
        float2 W = d_Wf[w * HH + tid];
        #pragma unroll
        for (int r = 0; r < 8; r++) {
            float xv = xs[r][w];
            ar[r] = fmaf(xv, W.x, ar[r]);
            ai[r] = fmaf(xv, W.y, ai[r]);
        }
    }
    #pragma unroll
    for (int r = 0; r < 8; r++)
        d_Y[im][(h0 + r) * HH + tid] = make_float2(ar[r], ai[r]);
}

// ---- forward DFT cols (R8 version) ----
__global__ __launch_bounds__(192) void k_fwd_cols() {
    int im = blockIdx.x, u0 = blockIdx.y * 8, tid = threadIdx.x;
    __shared__ float2 wt[8][HH];
    for (int j = tid; j < 8 * HH; j += 192)
        wt[j / HH][j % HH] = d_Wf[(u0 + j / HH) * HH + (j % HH)];
    __syncthreads();
    float fr[8], fi[8];
    #pragma unroll
    for (int r = 0; r < 8; r++) { fr[r] = 0.0f; fi[r] = 0.0f; }
    #pragma unroll 4
    for (int h = 0; h < HH; h++) {
        float2 y = d_Y[im][h * HH + tid];
        #pragma unroll
        for (int r = 0; r < 8; r++) {
            float2 w = wt[r][h];
            fr[r] = fmaf(w.x, y.x, fmaf(-w.y, y.y, fr[r]));
            fi[r] = fmaf(w.x, y.y, fmaf( w.y, y.x, fi[r]));
        }
    }
    #pragma unroll
    for (int r = 0; r < 8; r++)
        d_F[im][(u0 + r) * HH + tid] = make_float2(fr[r], fi[r]);
}

// ---- attention stats: mag staged once per pixel, then S + Gram ----
__global__ __launch_bounds__(192) void k_attn_stats(const float* w1, const float* b1) {
    int b = blockIdx.x, py = blockIdx.y, px0 = py * 64, tid = threadIdx.x;
    __shared__ float mags[3][64];
    __shared__ float h1s[64][65];
    {   // one sqrt per (cin, pixel): 192 threads cover 3*64
        int c = tid >> 6, p = tid & 63;
        int ip = (c == 0) ? 2 : (c - 1);          // channel fftshift perm
        float2 F = d_F[b * 3 + ip][px0 + p];
        mags[c][p] = sqrtf(F.x * F.x + F.y * F.y);
    }
    int hid = tid & 63, grp = tid >> 6;
    float w1a = w1[hid * 3], w1b = w1[hid * 3 + 1], w1c = w1[hid * 3 + 2], b1v = b1[hid];
    __syncthreads();
    for (int p = grp; p < 64; p += 3)
        h1s[hid][p] = fmaxf(fmaf(w1a, mags[0][p],
                       fmaf(w1b, mags[1][p], fmaf(w1c, mags[2][p], b1v))), 0.0f);
    __syncthreads();
    int blk = b * 576 + py;
    if (tid < 64) {
        float s = 0.0f;
        #pragma unroll 8
        for (int p = 0; p < 64; p++) s += h1s[tid][p];
        d_gpart[blk][NTILE * 16 + tid] = s;
    }
    if (tid < NTILE) {
        int J = 0, rem = tid;
        while (rem >= 16 - J) { rem -= 16 - J; J++; }
        int K = J + rem;
        float acc[4][4];
        #pragma unroll
        for (int a = 0; a < 4; a++)
            #pragma unroll
            for (int c = 0; c < 4; c++) acc[a][c] = 0.0f;
        #pragma unroll 2
        for (int p = 0; p < 64; p++) {
            float ra[4], rb[4];
            #pragma unroll
            for (int a = 0; a < 4; a++) ra[a] = h1s[J * 4 + a][p];
            #pragma unroll
            for (int c = 0; c < 4; c++) rb[c] = h1s[K * 4 + c][p];
            #pragma unroll
            for (int a = 0; a < 4; a++)
                #pragma unroll
                for (int c = 0; c < 4; c++)
                    acc[a][c] = fmaf(ra[a], rb[c], acc[a][c]);
        }
        #pragma unroll
        for (int a = 0; a < 4; a++)
            #pragma unroll
            for (int c = 0; c < 4; c++)
                d_gpart[blk][tid * 16 + a * 4 + c] = acc[a][c];
    }
}

// ---- attention h2 on quadrant pixels only (mag staged once) ----
__global__ __launch_bounds__(192) void k_attn_h2(const float* w1, const float* b1,
                                                 const float* w2, const float* b2) {
    int b = blockIdx.x, q0 = blockIdx.y * 64, tid = threadIdx.x;
    __shared__ float mags[3][64];
    __shared__ float h1s[64][64];
    {
        int c = tid >> 6, p = tid & 63;
        int q = q0 + p;
        int px = (q / QW) * HH + (q % QW);
        int ip = (c == 0) ? 2 : (c - 1);
        float2 F = d_F[b * 3 + ip][px];
        mags[c][p] = sqrtf(F.x * F.x + F.y * F.y);
    }
    int hid = tid & 63, grp = tid >> 6;
    float w1a = w1[hid * 3], w1b = w1[hid * 3 + 1], w1c = w1[hid * 3 + 2], b1v = b1[hid];
    __syncthreads();
    for (int p = grp; p < 64; p += 3)
        h1s[hid][p] = fmaxf(fmaf(w1a, mags[0][p],
                       fmaf(w1b, mags[1][p], fmaf(w1c, mags[2][p], b1v))), 0.0f);
    float w2row[64];
    #pragma unroll
    for (int j = 0; j < 64; j++) w2row[j] = w2[tid * 64 + j];
    float bias2 = b2[tid];
    __syncthreads();
    for (int g = 0; g < 16; g++) {
        float a0 = bias2, a1 = bias2, a2 = bias2, a3 = bias2;
        #pragma unroll
        for (int j = 0; j < 64; j++) {
            float4 h = *(const float4*)&h1s[j][g * 4];
            float wv = w2row[j];
            a0 = fmaf(wv, h.x, a0); a1 = fmaf(wv, h.y, a1);
            a2 = fmaf(wv, h.z, a2); a3 = fmaf(wv, h.w, a3);
        }
        long base = ((long)b * NQ + q0 + g * 4) * NCH + tid;
        d_h2q[base          ] = a0;
        d_h2q[base + NCH    ] = a1;
        d_h2q[base + 2 * NCH] = a2;
        d_h2q[base + 3 * NCH] = a3;
    }
}

// ---- Gram/S reduction, two deterministic stages ----
__global__ __launch_bounds__(256) void k_gred1() {
    int m = blockIdx.x;
    for (int e = threadIdx.x; e < GPW; e += 256) {
        double s = 0.0;
        for (int blk = m * 64; blk < m * 64 + 64; blk++)
            s += (double)d_gpart[blk][e];
        d_gmid[m][e] = s;
    }
}
__global__ __launch_bounds__(256) void k_gred2() {
    for (int e = threadIdx.x; e < GPW; e += 256) {
        double s = 0.0;
        for (int m = 0; m < 36; m++) s += d_gmid[m][e];
        if (e < NTILE * 16) d_Gd[e] = s;
        else d_Sd[e - NTILE * 16] = s;
    }
}

// ---- BN finalize via quadratic form ----
__global__ __launch_bounds__(64) void k_bnfin(const float* w2, const float* b2,
                                              const float* bnw, const float* bnb) {
    int c = blockIdx.x, j = threadIdx.x;
    __shared__ float w2s[64];
    __shared__ double sh1[64], sh2[64];
    w2s[j] = w2[c * 64 + j];
    __syncthreads();
    double wj = (double)w2s[j];
    double rowsum = 0.0;
    for (int k = 0; k < 64; k++) {
        int J = j >> 2, K = k >> 2, rj = j & 3, rk = k & 3;
        int off;
        if (J <= K) off = (J * 16 - (J * (J - 1)) / 2 + (K - J)) * 16 + rj * 4 + rk;
        else        off = (K * 16 - (K * (K - 1)) / 2 + (J - K)) * 16 + rk * 4 + rj;
        rowsum += d_Gd[off] * (double)w2s[k];
    }
    sh1[j] = wj * rowsum;
    sh2[j] = wj * d_Sd[j];
    __syncthreads();
    if (j == 0) {
        double quad = 0.0, ws = 0.0;
        for (int k = 0; k < 64; k++) { quad += sh1[k]; ws += sh2[k]; }
        double N   = (double)((long)NB * NPX);
        double b2c = (double)b2[c];
        double mu  = (ws + N * b2c) / N;
        double msq = (quad + 2.0 * b2c * ws + N * b2c * b2c) / N;
        double var = msq - mu * mu;
        float inv  = (float)(1.0 / sqrt(var + 1e-5));
        float A    = inv * bnw[c];
        d_bnA[c] = A;
        d_bnB[c] = bnb[c] - (float)mu * A;
    }
}

// ---- fused BN + softmax + gabor + A_tot (quadrant only) ----
__global__ __launch_bounds__(192) void k_atot() {
    int q = blockIdx.x, tid = threadIdx.x;
    int u = q / QW, v = q % QW;
    int px = u * HH + v;
    __shared__ float2 xsh[4][3];
    __shared__ float4 red4[6];
    __shared__ float2 red2[6];
    __shared__ float  pixsh[3];
    float A = d_bnA[tid], Bb = d_bnB[tid];
    float e0, e1, e2, e3;
    {
        long base = (long)q * NCH + tid;
        e0 = fexp(fmaf(d_h2q[base               ], A, Bb));
        e1 = fexp(fmaf(d_h2q[base + (long)NQ*NCH], A, Bb));
        e2 = fexp(fmaf(d_h2q[base + 2l*NQ*NCH   ], A, Bb));
        e3 = fexp(fmaf(d_h2q[base + 3l*NQ*NCH   ], A, Bb));
    }
    if (tid < 12) {
        int b = tid / 3, i = tid % 3;
        int ip = (i == 0) ? 2 : (i - 1);
        xsh[b][i] = d_F[b * 3 + ip][px];
    }
    if (tid == 12) { pixsh[0] = d_pix[0][px]; pixsh[1] = d_pix[1][px]; pixsh[2] = d_pix[2][px]; }
    float s0 = e0, s1 = e1, s2 = e2, s3 = e3;
    #pragma unroll
    for (int o = 16; o > 0; o >>= 1) {
        s0 += __shfl_xor_sync(0xffffffffu, s0, o);
        s1 += __shfl_xor_sync(0xffffffffu, s1, o);
        s2 += __shfl_xor_sync(0xffffffffu, s2, o);
        s3 += __shfl_xor_sync(0xffffffffu, s3, o);
    }
    __syncthreads();
    if ((tid & 31) == 0) red4[tid >> 5] = make_float4(s0, s1, s2, s3);
    __syncthreads();
    float4 S = red4[0];
    #pragma unroll
    for (int wI = 1; wI < 6; wI++) {
        float4 t = red4[wI];
        S.x += t.x; S.y += t.y; S.z += t.z; S.w += t.w;
    }
    float at0 = e0 / S.x, at1 = e1 / S.y, at2 = e2 / S.z, at3 = e3 / S.w;
    float L = pixsh[0], phi = pixsh[1], r = pixsh[2];
    float accr = 0.0f, acci = 0.0f;
    #pragma unroll
    for (int i = 0; i < 3; i++) {
        float ar = at0 * xsh[0][i].x + at1 * xsh[1][i].x + at2 * xsh[2][i].x + at3 * xsh[3][i].x;
        float ai = at0 * xsh[0][i].y + at1 * xsh[1][i].y + at2 * xsh[2][i].y + at3 * xsh[3][i].y;
        float4 pa = d_soiA[tid * 3 + i];
        float2 pb = d_soiB[tid * 3 + i];
        float dl = L - pa.x;
        float dp = phi - pa.z;
        float g = fexp(-(dl * dl) * pa.y - (dp * dp) * pa.w) * fcos(pb.x * r) * pb.y;
        accr = fmaf(g, ar, accr);
        acci = fmaf(g, ai, acci);
    }
    #pragma unroll
    for (int o = 16; o > 0; o >>= 1) {
        accr += __shfl_xor_sync(0xffffffffu, accr, o);
        acci += __shfl_xor_sync(0xffffffffu, acci, o);
    }
    __syncthreads();
    if ((tid & 31) == 0) red2[tid >> 5] = make_float2(accr, acci);
    __syncthreads();
    if (tid == 0) {
        float2 t = red2[0];
        #pragma unroll
        for (int wI = 1; wI < 6; wI++) { t.x += red2[wI].x; t.y += red2[wI].y; }
        d_A[q] = t;
    }
}

// ---- inverse DFT rows (R8 table version), quadrant-restricted, mask fused ----
__global__ __launch_bounds__(192) void k_inv_rows() {
    int o = blockIdx.x, u0 = blockIdx.y * 8, tid = threadIdx.x;
    int os = (o + 32) & 63;
    int lo0 = d_band[(os * 3 + 0) * 2] - 96, hi0 = d_band[(os * 3 + 0) * 2 + 1] - 96;
    int lo1 = d_band[(os * 3 + 1) * 2] - 96, hi1 = d_band[(os * 3 + 1) * 2 + 1] - 96;
    int lo2 = d_band[(os * 3 + 2) * 2] - 96, hi2 = d_band[(os * 3 + 2) * 2 + 1] - 96;
    __shared__ float2 qs[8][QW];
    for (int j = tid; j < 8 * QW; j += 192) {
        int r = j / QW, v = j % QW;
        int u = u0 + r;
        bool a0 = (u >= lo0) && (u < hi0), b0 = (v >= lo0) && (v < hi0);
        bool a1 = (u >= lo1) && (u < hi1), b1 = (v >= lo1) && (v < hi1);
        bool a2 = (u >= lo2) && (u < hi2), b2 = (v >= lo2) && (v < hi2);
        float m = (float)((a0 & b0) + (a1 & b1) + (a2 & b2));
        float2 a = d_A[u * QW + v];
        qs[r][v] = make_float2(a.x * m, a.y * m);
    }
    __syncthreads();
    float tr[8], ti[8];
    #pragma unroll
    for (int r = 0; r < 8; r++) { tr[r] = 0.0f; ti[r] = 0.0f; }
    #pragma unroll 4
    for (int v = 0; v < QW; v++) {
        float2 w = d_Wb[v * HH + tid];
        #pragma unroll
        for (int r = 0; r < 8; r++) {
            float2 qv = qs[r][v];
            tr[r] = fmaf(qv.x, w.x, fmaf(-qv.y, w.y, tr[r]));
            ti[r] = fmaf(qv.x, w.y, fmaf( qv.y, w.x, ti[r]));
        }
    }
    #pragma unroll
    for (int r = 0; r < 8; r++)
        d_T[o][(u0 + r) * HH + tid] = make_float2(tr[r], ti[r]);
}

// ---- inverse DFT cols (R8 version, real part) ----
__global__ __launch_bounds__(192) void k_inv_cols() {
    int o = blockIdx.x, s0 = blockIdx.y * 8, tid = threadIdx.x;
    __shared__ float2 wt[8][QW];
    for (int j = tid; j < 8 * QW; j += 192) {
        int r = j / QW, u = j % QW;
        wt[r][u] = d_Wb[(s0 + r) * HH + u];
    }
    __syncthreads();
    float acc[8];
    #pragma unroll
    for (int r = 0; r < 8; r++) acc[r] = 0.0f;
    #pragma unroll 4
    for (int u = 0; u < QW; u++) {
        float2 t = d_T[o][u * HH + tid];
        #pragma unroll
        for (int r = 0; r < 8; r++) {
            float2 w = wt[r][u];
            acc[r] = fmaf(w.x, t.x, fmaf(-w.y, t.y, acc[r]));
        }
    }
    #pragma unroll
    for (int r = 0; r < 8; r++)
        d_xf[o * NPX + (s0 + r) * HH + tid] = acc[r];
}

// ---- 3x3 conv + mixing ----
__global__ __launch_bounds__(256) void k_conv(const float* x, const float* cw,
                                              const float* mp, float* out) {
    int b = blockIdx.z;
    int h0 = blockIdx.y * 16, w0 = blockIdx.x * 16;
    int tx = threadIdx.x, ty = threadIdx.y;
    int t = ty * 16 + tx;
    __shared__ float xt[3][18][18];
    __shared__ float cws[64 * 27];
    for (int j = t; j < 972; j += 256) {
        int i = j / 324, rem = j % 324, hh = rem / 18, ww = rem % 18;
        int gh = h0 - 1 + hh, gw = w0 - 1 + ww;
        xt[i][hh][ww] = (gh >= 0 && gh < HH && gw >= 0 && gw < HH)
                        ? x[(b * 3 + i) * NPX + gh * HH + gw] : 0.0f;
    }
    for (int j = t; j < 1728; j += 256) cws[j] = cw[j];
    __syncthreads();
    float mix = mp[0];
    float win[27];
    #pragma unroll
    for (int i = 0; i < 3; i++)
        #pragma unroll
        for (int kh = 0; kh < 3; kh++)
            #pragma unroll
            for (int kw = 0; kw < 3; kw++)
                win[i * 9 + kh * 3 + kw] = xt[i][ty + kh][tx + kw];
    int pix = (h0 + ty) * HH + (w0 + tx);
    for (int o = 0; o < 64; o++) {
        float acc = 0.0f;
        #pragma unroll
        for (int j = 0; j < 27; j++) acc = fmaf(win[j], cws[o * 27 + j], acc);
        out[((b * 64 + o) * NPX) + pix] = fmaf(mix, d_xf[o * NPX + pix], (1.0f - mix) * acc);
    }
}

extern "C" void kernel_launch(void* const* d_in, const int* in_sizes, int n_in,
                              void* d_out, int out_size) {
    const float* x    = (const float*)d_in[0];
    const float* freq = (const float*)d_in[1];
    const float* thet = (const float*)d_in[2];
    const float* sigm = (const float*)d_in[3];
    const float* f0   = (const float*)d_in[4];
    const float* th0  = (const float*)d_in[5];
    const float* w1   = (const float*)d_in[6];
    const float* b1   = (const float*)d_in[7];
    const float* w2   = (const float*)d_in[8];
    const float* b2   = (const float*)d_in[9];
    const float* bnw  = (const float*)d_in[10];
    const float* bnb  = (const float*)d_in[11];
    const float* mp   = (const float*)d_in[12];
    const float* cw   = (const float*)d_in[13];
    const float* fbs  = (const float*)d_in[14];
    float* out = (float*)d_out;

    k_init<<<144, 256>>>(freq, thet, sigm, f0, th0, fbs);
    k_fwd_rows<<<dim3(12, 24), 192>>>(x);
    k_fwd_cols<<<dim3(12, 24), 192>>>();
    k_attn_stats<<<dim3(4, 576), 192>>>(w1, b1);
    k_attn_h2<<<dim3(4, 144), 192>>>(w1, b1, w2, b2);
    k_gred1<<<36, 256>>>();
    k_gred2<<<1, 256>>>();
    k_bnfin<<<192, 64>>>(w2, b2, bnw, bnb);
    k_atot<<<NQ, 192>>>();
    k_inv_rows<<<dim3(64, 12), 192>>>();
    k_inv_cols<<<dim3(64, 24), 192>>>();
    k_conv<<<dim3(12, 12, 4), dim3(16, 16)>>>(x, cw, mp, out);
}

// round 11
// speedup vs baseline: 1.2536x; 1.2523x over previous
#include <cuda_runtime.h>
#include <math.h>

#define HH  192
#define NPX 36864
#define NB  4
#define NCH 192
#define QW  96
#define NQ  9216          // 96*96 quadrant pixels
#define NT  1152          // stats tiles: 4 batches * 288 pixel-blocks (128 px each)
#define NTILE 136         // upper-triangular 4x4 tiles of 16x16 tile grid
#define GPW 2240          // 136*16 Gram entries + 64 S entries

__device__ float2 d_Wf[HH*HH];
__device__ float2 d_Wb[HH*HH];
__device__ float2 d_Y[12][NPX];
__device__ float2 d_F[12][NPX];
__device__ float  d_h2q[NB*NQ*NCH];
__device__ float  d_gpart[NT][GPW];
__device__ double d_gmid[36][GPW];
__device__ double d_Gd[NTILE*16];
__device__ double d_Sd[64];
__device__ float  d_bnA[NCH], d_bnB[NCH];
__device__ float2 d_A[NQ];
__device__ float2 d_T[64][QW*HH];
__device__ float  d_xf[64*NPX];
__device__ float4 d_soiA[576];
__device__ float2 d_soiB[576];
__device__ int    d_band[192*2];
__device__ float  d_pix[3][NPX];

// ---- FMA-poly transcendentals ----
__device__ __forceinline__ float fexp(float x) {
    if (!(x > -87.33654f)) return 0.0f;
    float y = x * 1.4426950408889634f;
    float n = rintf(y);
    float f = y - n;
    float p = 1.5403530e-4f;
    p = fmaf(p, f, 1.3333558e-3f);
    p = fmaf(p, f, 9.6181291e-3f);
    p = fmaf(p, f, 5.5504109e-2f);
    p = fmaf(p, f, 2.4022651e-1f);
    p = fmaf(p, f, 6.9314718e-1f);
    p = fmaf(p, f, 1.0f);
    return __int_as_float(((int)n + 127) << 23) * p;
}
__device__ __forceinline__ float fcos(float x) {   // |x| < ~6
    float qf = rintf(x * 0.6366197723675814f);
    int   q  = (int)qf;
    float t  = fmaf(qf, -1.5707963705062866f, x);
    t = fmaf(qf, 4.3711388e-8f, t);
    float s = t * t;
    float c = fmaf(s, fmaf(s, fmaf(s, 2.4433157e-5f, -1.3887316e-3f), 4.1666646e-2f), -0.5f);
    c = fmaf(c, s, 1.0f);
    float sn = t * fmaf(s, fmaf(s, fmaf(s, -1.9515296e-4f, 8.3321609e-3f), -1.6666655e-1f), 1.0f);
    int qm = q & 3;
    return (qm == 0) ? c : (qm == 1) ? -sn : (qm == 2) ? -c : sn;
}

// ---- fused init: DFT matrices + pixel grid + gabor params + bands ----
__global__ void k_init(const float* freq, const float* theta, const float* sigma,
                       const float* f0, const float* theta0, const float* fbs) {
    int idx = blockIdx.x * blockDim.x + threadIdx.x;
    if (idx >= NPX) return;
    {
        int k = idx / HH, n = idx % HH;
        int m = (k * n) % HH;
        float s, c;
        sincospif((float)m / 96.0f, &s, &c);
        d_Wf[idx] = make_float2(c, -s);
        d_Wb[idx] = make_float2(c * (1.0f / 192.0f), s * (1.0f / 192.0f));
    }
    {
        int u = idx / HH, v = idx % HH;
        int hs = (u >= 96) ? u - 96 : u + 96;
        int ws = (v >= 96) ? v - 96 : v + 96;
        float yy = -1.0f + hs * (2.0f / 191.0f);
        float xx = -1.0f + ws * (2.0f / 191.0f);
        float r  = sqrtf(xx * xx + yy * yy + 1e-6f);
        d_pix[0][idx] = logf(r);
        d_pix[1][idx] = atan2f(yy, xx);
        d_pix[2][idx] = r;
    }
    if (idx < 576) {
        float sg = sigma[idx], f0v = f0[idx], t0 = theta0[idx];
        float lf0 = logf(f0v);
        float dl  = logf(sg) - lf0;
        d_soiA[idx] = make_float4(lf0, 0.5f / (dl * dl), theta[idx], 0.5f / (t0 * t0));
        d_soiB[idx] = make_float2(freq[idx], 1.0f / (6.283185307179586f * sg * sg));
    }
    if (idx < 192) {
        d_band[idx * 2 + 0] = (int)floorf((fbs[idx * 2 + 0] + 1.0f) * 0.5f * 192.0f);
        d_band[idx * 2 + 1] = (int)floorf((fbs[idx * 2 + 1] + 1.0f) * 0.5f * 192.0f);
    }
}

// ---- forward DFT rows ----
__global__ __launch_bounds__(192) void k_fwd_rows(const float* x) {
    int im = blockIdx.x, h0 = blockIdx.y * 8, tid = threadIdx.x;
    __shared__ float xs[8][HH];
    const float* xim = x + im * NPX;
    for (int j = tid; j < 8 * HH; j += 192)
        xs[j / HH][j % HH] = xim[(h0 + j / HH) * HH + (j % HH)];
    __syncthreads();
    float ar[8], ai[8];
    #pragma unroll
    for (int r = 0; r < 8; r++) { ar[r] = 0.0f; ai[r] = 0.0f; }
    #pragma unroll 4
    for (int w = 0; w < HH; w++) {
        float2 W = d_Wf[w * HH + tid];
        #pragma unroll
        for (int r = 0; r < 8; r++) {
            float xv = xs[r][w];
            ar[r] = fmaf(xv, W.x, ar[r]);
            ai[r] = fmaf(xv, W.y, ai[r]);
        }
    }
    #pragma unroll
    for (int r = 0; r < 8; r++)
        d_Y[im][(h0 + r) * HH + tid] = make_float2(ar[r], ai[r]);
}

// ---- forward DFT cols ----
__global__ __launch_bounds__(192) void k_fwd_cols() {
    int im = blockIdx.x, u0 = blockIdx.y * 8, tid = threadIdx.x;
    __shared__ float2 wt[8][HH];
    for (int j = tid; j < 8 * HH; j += 192)
        wt[j / HH][j % HH] = d_Wf[(u0 + j / HH) * HH + (j % HH)];
    __syncthreads();
    float fr[8], fi[8];
    #pragma unroll
    for (int r = 0; r < 8; r++) { fr[r] = 0.0f; fi[r] = 0.0f; }
    #pragma unroll 4
    for (int h = 0; h < HH; h++) {
        float2 y = d_Y[im][h * HH + tid];
        #pragma unroll
        for (int r = 0; r < 8; r++) {
            float2 w = wt[r][h];
            fr[r] = fmaf(w.x, y.x, fmaf(-w.y, y.y, fr[r]));
            fi[r] = fmaf(w.x, y.y, fmaf( w.y, y.x, fi[r]));
        }
    }
    #pragma unroll
    for (int r = 0; r < 8; r++)
        d_F[im][(u0 + r) * HH + tid] = make_float2(fr[r], fi[r]);
}

// ---- attention stats: 128-px tiles, pixel-major h1, float4 Gram ----
__global__ __launch_bounds__(192) void k_attn_stats(const float* w1, const float* b1) {
    int b = blockIdx.x, py = blockIdx.y, px0 = py * 128, tid = threadIdx.x;
    __shared__ float mags[3][128];
    __shared__ __align__(16) float h1t[128][64];   // pixel-major
    for (int jj = tid; jj < 384; jj += 192) {
        int c = jj >> 7, p = jj & 127;
        int ip = (c == 0) ? 2 : (c - 1);           // channel fftshift perm
        float2 F = d_F[b * 3 + ip][px0 + p];
        mags[c][p] = sqrtf(F.x * F.x + F.y * F.y);
    }
    int hid = tid & 63, grp = tid >> 6;
    float w1a = w1[hid * 3], w1b = w1[hid * 3 + 1], w1c = w1[hid * 3 + 2], b1v = b1[hid];
    __syncthreads();
    for (int p = grp; p < 128; p += 3)
        h1t[p][hid] = fmaxf(fmaf(w1a, mags[0][p],
                       fmaf(w1b, mags[1][p], fmaf(w1c, mags[2][p], b1v))), 0.0f);
    __syncthreads();
    int blk = b * 288 + py;
    if (tid < 64) {
        float s = 0.0f;
        #pragma unroll 8
        for (int p = 0; p < 128; p++) s += h1t[p][tid];
        d_gpart[blk][NTILE * 16 + tid] = s;
    }
    if (tid < NTILE) {
        int J = 0, rem = tid;
        while (rem >= 16 - J) { rem -= 16 - J; J++; }
        int K = J + rem;
        float acc[4][4];
        #pragma unroll
        for (int a = 0; a < 4; a++)
            #pragma unroll
            for (int c = 0; c < 4; c++) acc[a][c] = 0.0f;
        #pragma unroll 4
        for (int p = 0; p < 128; p++) {
            float4 ra = *(const float4*)&h1t[p][J * 4];
            float4 rb = *(const float4*)&h1t[p][K * 4];
            acc[0][0] = fmaf(ra.x, rb.x, acc[0][0]);
            acc[0][1] = fmaf(ra.x, rb.y, acc[0][1]);
            acc[0][2] = fmaf(ra.x, rb.z, acc[0][2]);
            acc[0][3] = fmaf(ra.x, rb.w, acc[0][3]);
            acc[1][0] = fmaf(ra.y, rb.x, acc[1][0]);
            acc[1][1] = fmaf(ra.y, rb.y, acc[1][1]);
            acc[1][2] = fmaf(ra.y, rb.z, acc[1][2]);
            acc[1][3] = fmaf(ra.y, rb.w, acc[1][3]);
            acc[2][0] = fmaf(ra.z, rb.x, acc[2][0]);
            acc[2][1] = fmaf(ra.z, rb.y, acc[2][1]);
            acc[2][2] = fmaf(ra.z, rb.z, acc[2][2]);
            acc[2][3] = fmaf(ra.z, rb.w, acc[2][3]);
            acc[3][0] = fmaf(ra.w, rb.x, acc[3][0]);
            acc[3][1] = fmaf(ra.w, rb.y, acc[3][1]);
            acc[3][2] = fmaf(ra.w, rb.z, acc[3][2]);
            acc[3][3] = fmaf(ra.w, rb.w, acc[3][3]);
        }
        #pragma unroll
        for (int a = 0; a < 4; a++)
            #pragma unroll
            for (int c = 0; c < 4; c++)
                d_gpart[blk][tid * 16 + a * 4 + c] = acc[a][c];
    }
}

// ---- attention h2 on quadrant pixels only (mag staged once) ----
__global__ __launch_bounds__(192) void k_attn_h2(const float* w1, const float* b1,
                                                 const float* w2, const float* b2) {
    int b = blockIdx.x, q0 = blockIdx.y * 64, tid = threadIdx.x;
    __shared__ float mags[3][64];
    __shared__ float h1s[64][64];
    {
        int c = tid >> 6, p = tid & 63;
        int q = q0 + p;
        int px = (q / QW) * HH + (q % QW);
        int ip = (c == 0) ? 2 : (c - 1);
        float2 F = d_F[b * 3 + ip][px];
        mags[c][p] = sqrtf(F.x * F.x + F.y * F.y);
    }
    int hid = tid & 63, grp = tid >> 6;
    float w1a = w1[hid * 3], w1b = w1[hid * 3 + 1], w1c = w1[hid * 3 + 2], b1v = b1[hid];
    __syncthreads();
    for (int p = grp; p < 64; p += 3)
        h1s[hid][p] = fmaxf(fmaf(w1a, mags[0][p],
                       fmaf(w1b, mags[1][p], fmaf(w1c, mags[2][p], b1v))), 0.0f);
    float w2row[64];
    #pragma unroll
    for (int j = 0; j < 64; j++) w2row[j] = w2[tid * 64 + j];
    float bias2 = b2[tid];
    __syncthreads();
    for (int g = 0; g < 16; g++) {
        float a0 = bias2, a1 = bias2, a2 = bias2, a3 = bias2;
        #pragma unroll
        for (int j = 0; j < 64; j++) {
            float4 h = *(const float4*)&h1s[j][g * 4];
            float wv = w2row[j];
            a0 = fmaf(wv, h.x, a0); a1 = fmaf(wv, h.y, a1);
            a2 = fmaf(wv, h.z, a2); a3 = fmaf(wv, h.w, a3);
        }
        long base = ((long)b * NQ + q0 + g * 4) * NCH + tid;
        d_h2q[base          ] = a0;
        d_h2q[base + NCH    ] = a1;
        d_h2q[base + 2 * NCH] = a2;
        d_h2q[base + 3 * NCH] = a3;
    }
}

// ---- Gram/S reduction, two deterministic stages ----
__global__ __launch_bounds__(256) void k_gred1() {
    int m = blockIdx.x;
    for (int e = threadIdx.x; e < GPW; e += 256) {
        double s = 0.0;
        for (int blk = m * 32; blk < m * 32 + 32; blk++)
            s += (double)d_gpart[blk][e];
        d_gmid[m][e] = s;
    }
}
__global__ __launch_bounds__(256) void k_gred2() {
    for (int e = threadIdx.x; e < GPW; e += 256) {
        double s = 0.0;
        for (int m = 0; m < 36; m++) s += d_gmid[m][e];
        if (e < NTILE * 16) d_Gd[e] = s;
        else d_Sd[e - NTILE * 16] = s;
    }
}

// ---- BN finalize via quadratic form ----
__global__ __launch_bounds__(64) void k_bnfin(const float* w2, const float* b2,
                                              const float* bnw, const float* bnb) {
    int c = blockIdx.x, j = threadIdx.x;
    __shared__ float w2s[64];
    __shared__ double sh1[64], sh2[64];
    w2s[j] = w2[c * 64 + j];
    __syncthreads();
    double wj = (double)w2s[j];
    double rowsum = 0.0;
    for (int k = 0; k < 64; k++) {
        int J = j >> 2, K = k >> 2, rj = j & 3, rk = k & 3;
        int off;
        if (J <= K) off = (J * 16 - (J * (J - 1)) / 2 + (K - J)) * 16 + rj * 4 + rk;
        else        off = (K * 16 - (K * (K - 1)) / 2 + (J - K)) * 16 + rk * 4 + rj;
        rowsum += d_Gd[off] * (double)w2s[k];
    }
    sh1[j] = wj * rowsum;
    sh2[j] = wj * d_Sd[j];
    __syncthreads();
    if (j == 0) {
        double quad = 0.0, ws = 0.0;
        for (int k = 0; k < 64; k++) { quad += sh1[k]; ws += sh2[k]; }
        double N   = (double)((long)NB * NPX);
        double b2c = (double)b2[c];
        double mu  = (ws + N * b2c) / N;
        double msq = (quad + 2.0 * b2c * ws + N * b2c * b2c) / N;
        double var = msq - mu * mu;
        float inv  = (float)(1.0 / sqrt(var + 1e-5));
        float A    = inv * bnw[c];
        d_bnA[c] = A;
        d_bnB[c] = bnb[c] - (float)mu * A;
    }
}

// ---- fused BN + softmax + gabor + A_tot: warp-per-pixel, no barriers ----
__global__ __launch_bounds__(192) void k_atot() {
    int wid = threadIdx.x >> 5, lane = threadIdx.x & 31;
    int q = blockIdx.x * 6 + wid;                  // NQ = 1536*6
    int u = q / QW, v = q % QW;
    int px = u * HH + v;
    // stage Xs (12 complex) and pixel coords via lanes + shuffles
    float2 Fv = make_float2(0.0f, 0.0f);
    if (lane < 12) {
        int b = lane / 3, i = lane % 3;
        int ip = (i == 0) ? 2 : (i - 1);
        Fv = d_F[b * 3 + ip][px];
    }
    float pv = (lane < 3) ? d_pix[lane][px] : 0.0f;
    float L   = __shfl_sync(0xffffffffu, pv, 0);
    float phi = __shfl_sync(0xffffffffu, pv, 1);
    float rr  = __shfl_sync(0xffffffffu, pv, 2);
    float Xr[4][3], Xi[4][3];
    #pragma unroll
    for (int b = 0; b < 4; b++)
        #pragma unroll
        for (int i = 0; i < 3; i++) {
            Xr[b][i] = __shfl_sync(0xffffffffu, Fv.x, b * 3 + i);
            Xi[b][i] = __shfl_sync(0xffffffffu, Fv.y, b * 3 + i);
        }
    // BN params for this lane's 6 channels (c = lane + 32k)
    float bnA[6], bnB[6];
    #pragma unroll
    for (int k = 0; k < 6; k++) {
        bnA[k] = d_bnA[lane + 32 * k];
        bnB[k] = d_bnB[lane + 32 * k];
    }
    // exp(BN(h2)) and per-batch softmax denominators (warp reductions)
    float e[4][6], ssum[4];
    #pragma unroll
    for (int b = 0; b < 4; b++) {
        long base = ((long)b * NQ + q) * NCH + lane;
        float ls = 0.0f;
        #pragma unroll
        for (int k = 0; k < 6; k++) {
            e[b][k] = fexp(fmaf(d_h2q[base + 32 * k], bnA[k], bnB[k]));
            ls += e[b][k];
        }
        #pragma unroll
        for (int o = 16; o > 0; o >>= 1) ls += __shfl_xor_sync(0xffffffffu, ls, o);
        ssum[b] = ls;
    }
    float i0 = 1.0f / ssum[0], i1 = 1.0f / ssum[1], i2 = 1.0f / ssum[2], i3 = 1.0f / ssum[3];
    float accr = 0.0f, acci = 0.0f;
    #pragma unroll
    for (int k = 0; k < 6; k++) {
        int c = lane + 32 * k;
        float w0 = e[0][k] * i0, w1 = e[1][k] * i1, w2v = e[2][k] * i2, w3 = e[3][k] * i3;
        #pragma unroll
        for (int i = 0; i < 3; i++) {
            float ar = w0 * Xr[0][i] + w1 * Xr[1][i] + w2v * Xr[2][i] + w3 * Xr[3][i];
            float ai = w0 * Xi[0][i] + w1 * Xi[1][i] + w2v * Xi[2][i] + w3 * Xi[3][i];
            float4 pa = d_soiA[c * 3 + i];
            float2 pb = d_soiB[c * 3 + i];
            float dl = L - pa.x;
            float dp = phi - pa.z;
            float g = fexp(-(dl * dl) * pa.y - (dp * dp) * pa.w) * fcos(pb.x * rr) * pb.y;
            accr = fmaf(g, ar, accr);
            acci = fmaf(g, ai, acci);
        }
    }
    #pragma unroll
    for (int o = 16; o > 0; o >>= 1) {
        accr += __shfl_xor_sync(0xffffffffu, accr, o);
        acci += __shfl_xor_sync(0xffffffffu, acci, o);
    }
    if (lane == 0) d_A[q] = make_float2(accr, acci);
}

// ---- inverse DFT rows, quadrant-restricted, mask fused ----
__global__ __launch_bounds__(192) void k_inv_rows() {
    int o = blockIdx.x, u0 = blockIdx.y * 8, tid = threadIdx.x;
    int os = (o + 32) & 63;
    int lo0 = d_band[(os * 3 + 0) * 2] - 96, hi0 = d_band[(os * 3 + 0) * 2 + 1] - 96;
    int lo1 = d_band[(os * 3 + 1) * 2] - 96, hi1 = d_band[(os * 3 + 1) * 2 + 1] - 96;
    int lo2 = d_band[(os * 3 + 2) * 2] - 96, hi2 = d_band[(os * 3 + 2) * 2 + 1] - 96;
    __shared__ float2 qs[8][QW];
    for (int j = tid; j < 8 * QW; j += 192) {
        int r = j / QW, v = j % QW;
        int u = u0 + r;
        bool a0 = (u >= lo0) && (u < hi0), b0 = (v >= lo0) && (v < hi0);
        bool a1 = (u >= lo1) && (u < hi1), b1 = (v >= lo1) && (v < hi1);
        bool a2 = (u >= lo2) && (u < hi2), b2 = (v >= lo2) && (v < hi2);
        float m = (float)((a0 & b0) + (a1 & b1) + (a2 & b2));
        float2 a = d_A[u * QW + v];
        qs[r][v] = make_float2(a.x * m, a.y * m);
    }
    __syncthreads();
    float tr[8], ti[8];
    #pragma unroll
    for (int r = 0; r < 8; r++) { tr[r] = 0.0f; ti[r] = 0.0f; }
    #pragma unroll 4
    for (int v = 0; v < QW; v++) {
        float2 w = d_Wb[v * HH + tid];
        #pragma unroll
        for (int r = 0; r < 8; r++) {
            float2 qv = qs[r][v];
            tr[r] = fmaf(qv.x, w.x, fmaf(-qv.y, w.y, tr[r]));
            ti[r] = fmaf(qv.x, w.y, fmaf( qv.y, w.x, ti[r]));
        }
    }
    #pragma unroll
    for (int r = 0; r < 8; r++)
        d_T[o][(u0 + r) * HH + tid] = make_float2(tr[r], ti[r]);
}

// ---- inverse DFT cols (real part), u-sum over [0,96) ----
__global__ __launch_bounds__(192) void k_inv_cols() {
    int o = blockIdx.x, s0 = blockIdx.y * 8, tid = threadIdx.x;
    __shared__ float2 wt[8][QW];
    for (int j = tid; j < 8 * QW; j += 192) {
        int r = j / QW, u = j % QW;
        wt[r][u] = d_Wb[(s0 + r) * HH + u];
    }
    __syncthreads();
    float acc[8];
    #pragma unroll
    for (int r = 0; r < 8; r++) acc[r] = 0.0f;
    #pragma unroll 4
    for (int u = 0; u < QW; u++) {
        float2 t = d_T[o][u * HH + tid];
        #pragma unroll
        for (int r = 0; r < 8; r++) {
            float2 w = wt[r][u];
            acc[r] = fmaf(w.x, t.x, fmaf(-w.y, t.y, acc[r]));
        }
    }
    #pragma unroll
    for (int r = 0; r < 8; r++)
        d_xf[o * NPX + (s0 + r) * HH + tid] = acc[r];
}

// ---- 3x3 conv + mixing ----
__global__ __launch_bounds__(256) void k_conv(const float* x, const float* cw,
                                              const float* mp, float* out) {
    int b = blockIdx.z;
    int h0 = blockIdx.y * 16, w0 = blockIdx.x * 16;
    int tx = threadIdx.x, ty = threadIdx.y;
    int t = ty * 16 + tx;
    __shared__ float xt[3][18][18];
    __shared__ float cws[64 * 27];
    for (int j = t; j < 972; j += 256) {
        int i = j / 324, rem = j % 324, hh = rem / 18, ww = rem % 18;
        int gh = h0 - 1 + hh, gw = w0 - 1 + ww;
        xt[i][hh][ww] = (gh >= 0 && gh < HH && gw >= 0 && gw < HH)
                        ? x[(b * 3 + i) * NPX + gh * HH + gw] : 0.0f;
    }
    for (int j = t; j < 1728; j += 256) cws[j] = cw[j];
    __syncthreads();
    float mix = mp[0];
    float win[27];
    #pragma unroll
    for (int i = 0; i < 3; i++)
        #pragma unroll
        for (int kh = 0; kh < 3; kh++)
            #pragma unroll
            for (int kw = 0; kw < 3; kw++)
                win[i * 9 + kh * 3 + kw] = xt[i][ty + kh][tx + kw];
    int pix = (h0 + ty) * HH + (w0 + tx);
    for (int o = 0; o < 64; o++) {
        float acc = 0.0f;
        #pragma unroll
        for (int j = 0; j < 27; j++) acc = fmaf(win[j], cws[o * 27 + j], acc);
        out[((b * 64 + o) * NPX) + pix] = fmaf(mix, d_xf[o * NPX + pix], (1.0f - mix) * acc);
    }
}

extern "C" void kernel_launch(void* const* d_in, const int* in_sizes, int n_in,
                              void* d_out, int out_size) {
    const float* x    = (const float*)d_in[0];
    const float* freq = (const float*)d_in[1];
    const float* thet = (const float*)d_in[2];
    const float* sigm = (const float*)d_in[3];
    const float* f0   = (const float*)d_in[4];
    const float* th0  = (const float*)d_in[5];
    const float* w1   = (const float*)d_in[6];
    const float* b1   = (const float*)d_in[7];
    const float* w2   = (const float*)d_in[8];
    const float* b2   = (const float*)d_in[9];
    const float* bnw  = (const float*)d_in[10];
    const float* bnb  = (const float*)d_in[11];
    const float* mp   = (const float*)d_in[12];
    const float* cw   = (const float*)d_in[13];
    const float* fbs  = (const float*)d_in[14];
    float* out = (float*)d_out;

    k_init<<<144, 256>>>(freq, thet, sigm, f0, th0, fbs);
    k_fwd_rows<<<dim3(12, 24), 192>>>(x);
    k_fwd_cols<<<dim3(12, 24), 192>>>();
    k_attn_stats<<<dim3(4, 288), 192>>>(w1, b1);
    k_attn_h2<<<dim3(4, 144), 192>>>(w1, b1, w2, b2);
    k_gred1<<<36, 256>>>();
    k_gred2<<<1, 256>>>();
    k_bnfin<<<192, 64>>>(w2, b2, bnw, bnb);
    k_atot<<<1536, 192>>>();
    k_inv_rows<<<dim3(64, 12), 192>>>();
    k_inv_cols<<<dim3(64, 24), 192>>>();
    k_conv<<<dim3(12, 12, 4), dim3(16, 16)>>>(x, cw, mp, out);
}

// round 12
// speedup vs baseline: 1.4032x; 1.1193x over previous
#include <cuda_runtime.h>
#include <math.h>

#define HH  192
#define NPX 36864
#define NB  4
#define NCH 192
#define QW  96
#define NQ  9216          // 96*96 quadrant pixels
#define NT  1152          // stats tiles: 4 batches * 288 pixel-blocks (128 px each)
#define NTILE 136         // upper-triangular 4x4 tiles of 16x16 tile grid
#define GPW 2240          // 136*16 Gram entries + 64 S entries

__device__ float2 d_Wf[HH*HH];
__device__ float2 d_Wb[HH*HH];
__device__ float2 d_Y[12][NPX];
__device__ float2 d_F[12][NPX];
__device__ float  d_h2q[NB*NQ*NCH];
__device__ float  d_gpart[NT][GPW];
__device__ double d_gmid[36][GPW];
__device__ double d_Gd[NTILE*16];
__device__ double d_Sd[64];
__device__ float  d_bnA[NCH], d_bnB[NCH];
__device__ float2 d_A[NQ];
__device__ float2 d_T[64][QW*HH];
__device__ float  d_xf[64*NPX];
__device__ float4 d_soiA[576];
__device__ float2 d_soiB[576];
__device__ int    d_band[192*2];
__device__ float  d_pix[3][NPX];

// ---- FMA-poly transcendentals ----
__device__ __forceinline__ float fexp(float x) {
    if (!(x > -87.33654f)) return 0.0f;
    float y = x * 1.4426950408889634f;
    float n = rintf(y);
    float f = y - n;
    float p = 1.5403530e-4f;
    p = fmaf(p, f, 1.3333558e-3f);
    p = fmaf(p, f, 9.6181291e-3f);
    p = fmaf(p, f, 5.5504109e-2f);
    p = fmaf(p, f, 2.4022651e-1f);
    p = fmaf(p, f, 6.9314718e-1f);
    p = fmaf(p, f, 1.0f);
    return __int_as_float(((int)n + 127) << 23) * p;
}
__device__ __forceinline__ float fcos(float x) {   // |x| < ~6
    float qf = rintf(x * 0.6366197723675814f);
    int   q  = (int)qf;
    float t  = fmaf(qf, -1.5707963705062866f, x);
    t = fmaf(qf, 4.3711388e-8f, t);
    float s = t * t;
    float c = fmaf(s, fmaf(s, fmaf(s, 2.4433157e-5f, -1.3887316e-3f), 4.1666646e-2f), -0.5f);
    c = fmaf(c, s, 1.0f);
    float sn = t * fmaf(s, fmaf(s, fmaf(s, -1.9515296e-4f, 8.3321609e-3f), -1.6666655e-1f), 1.0f);
    int qm = q & 3;
    return (qm == 0) ? c : (qm == 1) ? -sn : (qm == 2) ? -c : sn;
}

// ---- fused init ----
__global__ void k_init(const float* freq, const float* theta, const float* sigma,
                       const float* f0, const float* theta0, const float* fbs) {
    int idx = blockIdx.x * blockDim.x + threadIdx.x;
    if (idx >= NPX) return;
    {
        int k = idx / HH, n = idx % HH;
        int m = (k * n) % HH;
        float s, c;
        sincospif((float)m / 96.0f, &s, &c);
        d_Wf[idx] = make_float2(c, -s);
        d_Wb[idx] = make_float2(c * (1.0f / 192.0f), s * (1.0f / 192.0f));
    }
    {
        int u = idx / HH, v = idx % HH;
        int hs = (u >= 96) ? u - 96 : u + 96;
        int ws = (v >= 96) ? v - 96 : v + 96;
        float yy = -1.0f + hs * (2.0f / 191.0f);
        float xx = -1.0f + ws * (2.0f / 191.0f);
        float r  = sqrtf(xx * xx + yy * yy + 1e-6f);
        d_pix[0][idx] = logf(r);
        d_pix[1][idx] = atan2f(yy, xx);
        d_pix[2][idx] = r;
    }
    if (idx < 576) {
        float sg = sigma[idx], f0v = f0[idx], t0 = theta0[idx];
        float lf0 = logf(f0v);
        float dl  = logf(sg) - lf0;
        d_soiA[idx] = make_float4(lf0, 0.5f / (dl * dl), theta[idx], 0.5f / (t0 * t0));
        d_soiB[idx] = make_float2(freq[idx], 1.0f / (6.283185307179586f * sg * sg));
    }
    if (idx < 192) {
        d_band[idx * 2 + 0] = (int)floorf((fbs[idx * 2 + 0] + 1.0f) * 0.5f * 192.0f);
        d_band[idx * 2 + 1] = (int)floorf((fbs[idx * 2 + 1] + 1.0f) * 0.5f * 192.0f);
    }
}

// ---- forward DFT rows: R=4 for occupancy ----
__global__ __launch_bounds__(192) void k_fwd_rows(const float* x) {
    int im = blockIdx.x, h0 = blockIdx.y * 4, tid = threadIdx.x;
    __shared__ float xs[4][HH];
    const float* xim = x + im * NPX;
    for (int j = tid; j < 4 * HH; j += 192)
        xs[j / HH][j % HH] = xim[(h0 + j / HH) * HH + (j % HH)];
    __syncthreads();
    float ar[4], ai[4];
    #pragma unroll
    for (int r = 0; r < 4; r++) { ar[r] = 0.0f; ai[r] = 0.0f; }
    #pragma unroll 8
    for (int w = 0; w < HH; w++) {
        float2 W = d_Wf[w * HH + tid];
        #pragma unroll
        for (int r = 0; r < 4; r++) {
            float xv = xs[r][w];
            ar[r] = fmaf(xv, W.x, ar[r]);
            ai[r] = fmaf(xv, W.y, ai[r]);
        }
    }
    #pragma unroll
    for (int r = 0; r < 4; r++)
        d_Y[im][(h0 + r) * HH + tid] = make_float2(ar[r], ai[r]);
}

// ---- forward DFT cols: R=4 ----
__global__ __launch_bounds__(192) void k_fwd_cols() {
    int im = blockIdx.x, u0 = blockIdx.y * 4, tid = threadIdx.x;
    __shared__ float2 wt[4][HH];
    for (int j = tid; j < 4 * HH; j += 192)
        wt[j / HH][j % HH] = d_Wf[(u0 + j / HH) * HH + (j % HH)];
    __syncthreads();
    float fr[4], fi[4];
    #pragma unroll
    for (int r = 0; r < 4; r++) { fr[r] = 0.0f; fi[r] = 0.0f; }
    #pragma unroll 8
    for (int h = 0; h < HH; h++) {
        float2 y = d_Y[im][h * HH + tid];
        #pragma unroll
        for (int r = 0; r < 4; r++) {
            float2 w = wt[r][h];
            fr[r] = fmaf(w.x, y.x, fmaf(-w.y, y.y, fr[r]));
            fi[r] = fmaf(w.x, y.y, fmaf( w.y, y.x, fi[r]));
        }
    }
    #pragma unroll
    for (int r = 0; r < 4; r++)
        d_F[im][(u0 + r) * HH + tid] = make_float2(fr[r], fi[r]);
}

// ---- attention stats: 128-px tiles, pixel-major h1, float4 Gram ----
__global__ __launch_bounds__(192) void k_attn_stats(const float* w1, const float* b1) {
    int b = blockIdx.x, py = blockIdx.y, px0 = py * 128, tid = threadIdx.x;
    __shared__ float mags[3][128];
    __shared__ __align__(16) float h1t[128][64];   // pixel-major
    for (int jj = tid; jj < 384; jj += 192) {
        int c = jj >> 7, p = jj & 127;
        int ip = (c == 0) ? 2 : (c - 1);           // channel fftshift perm
        float2 F = d_F[b * 3 + ip][px0 + p];
        mags[c][p] = sqrtf(F.x * F.x + F.y * F.y);
    }
    int hid = tid & 63, grp = tid >> 6;
    float w1a = w1[hid * 3], w1b = w1[hid * 3 + 1], w1c = w1[hid * 3 + 2], b1v = b1[hid];
    __syncthreads();
    for (int p = grp; p < 128; p += 3)
        h1t[p][hid] = fmaxf(fmaf(w1a, mags[0][p],
                       fmaf(w1b, mags[1][p], fmaf(w1c, mags[2][p], b1v))), 0.0f);
    __syncthreads();
    int blk = b * 288 + py;
    if (tid < 64) {
        float s = 0.0f;
        #pragma unroll 8
        for (int p = 0; p < 128; p++) s += h1t[p][tid];
        d_gpart[blk][NTILE * 16 + tid] = s;
    }
    if (tid < NTILE) {
        int J = 0, rem = tid;
        while (rem >= 16 - J) { rem -= 16 - J; J++; }
        int K = J + rem;
        float acc[4][4];
        #pragma unroll
        for (int a = 0; a < 4; a++)
            #pragma unroll
            for (int c = 0; c < 4; c++) acc[a][c] = 0.0f;
        #pragma unroll 4
        for (int p = 0; p < 128; p++) {
            float4 ra = *(const float4*)&h1t[p][J * 4];
            float4 rb = *(const float4*)&h1t[p][K * 4];
            acc[0][0] = fmaf(ra.x, rb.x, acc[0][0]);
            acc[0][1] = fmaf(ra.x, rb.y, acc[0][1]);
            acc[0][2] = fmaf(ra.x, rb.z, acc[0][2]);
            acc[0][3] = fmaf(ra.x, rb.w, acc[0][3]);
            acc[1][0] = fmaf(ra.y, rb.x, acc[1][0]);
            acc[1][1] = fmaf(ra.y, rb.y, acc[1][1]);
            acc[1][2] = fmaf(ra.y, rb.z, acc[1][2]);
            acc[1][3] = fmaf(ra.y, rb.w, acc[1][3]);
            acc[2][0] = fmaf(ra.z, rb.x, acc[2][0]);
            acc[2][1] = fmaf(ra.z, rb.y, acc[2][1]);
            acc[2][2] = fmaf(ra.z, rb.z, acc[2][2]);
            acc[2][3] = fmaf(ra.z, rb.w, acc[2][3]);
            acc[3][0] = fmaf(ra.w, rb.x, acc[3][0]);
            acc[3][1] = fmaf(ra.w, rb.y, acc[3][1]);
            acc[3][2] = fmaf(ra.w, rb.z, acc[3][2]);
            acc[3][3] = fmaf(ra.w, rb.w, acc[3][3]);
        }
        #pragma unroll
        for (int a = 0; a < 4; a++)
            #pragma unroll
            for (int c = 0; c < 4; c++)
                d_gpart[blk][tid * 16 + a * 4 + c] = acc[a][c];
    }
}

// ---- attention h2: 128-px quadrant tiles, padded h1 ----
__global__ __launch_bounds__(192) void k_attn_h2(const float* w1, const float* b1,
                                                 const float* w2, const float* b2) {
    int b = blockIdx.x, q0 = blockIdx.y * 128, tid = threadIdx.x;
    __shared__ float mags[3][128];
    __shared__ __align__(16) float h1s[64][132];   // hid-major, pad 132
    for (int jj = tid; jj < 384; jj += 192) {
        int c = jj >> 7, p = jj & 127;
        int q = q0 + p;
        int px = (q / QW) * HH + (q % QW);
        int ip = (c == 0) ? 2 : (c - 1);
        float2 F = d_F[b * 3 + ip][px];
        mags[c][p] = sqrtf(F.x * F.x + F.y * F.y);
    }
    int hid = tid & 63, grp = tid >> 6;
    float w1a = w1[hid * 3], w1b = w1[hid * 3 + 1], w1c = w1[hid * 3 + 2], b1v = b1[hid];
    __syncthreads();
    for (int p = grp; p < 128; p += 3)
        h1s[hid][p] = fmaxf(fmaf(w1a, mags[0][p],
                       fmaf(w1b, mags[1][p], fmaf(w1c, mags[2][p], b1v))), 0.0f);
    float w2row[64];
    #pragma unroll
    for (int j = 0; j < 64; j++) w2row[j] = w2[tid * 64 + j];
    float bias2 = b2[tid];
    __syncthreads();
    for (int g = 0; g < 32; g++) {
        float a0 = bias2, a1 = bias2, a2 = bias2, a3 = bias2;
        #pragma unroll
        for (int j = 0; j < 64; j++) {
            float4 h = *(const float4*)&h1s[j][g * 4];
            float wv = w2row[j];
            a0 = fmaf(wv, h.x, a0); a1 = fmaf(wv, h.y, a1);
            a2 = fmaf(wv, h.z, a2); a3 = fmaf(wv, h.w, a3);
        }
        long base = ((long)b * NQ + q0 + g * 4) * NCH + tid;
        d_h2q[base          ] = a0;
        d_h2q[base + NCH    ] = a1;
        d_h2q[base + 2 * NCH] = a2;
        d_h2q[base + 3 * NCH] = a3;
    }
}

// ---- Gram/S reduction ----
__global__ __launch_bounds__(256) void k_gred1() {
    int m = blockIdx.x;
    for (int e = threadIdx.x; e < GPW; e += 256) {
        double s = 0.0;
        for (int blk = m * 32; blk < m * 32 + 32; blk++)
            s += (double)d_gpart[blk][e];
        d_gmid[m][e] = s;
    }
}
__global__ __launch_bounds__(256) void k_gred2() {
    for (int e = threadIdx.x; e < GPW; e += 256) {
        double s = 0.0;
        for (int m = 0; m < 36; m++) s += d_gmid[m][e];
        if (e < NTILE * 16) d_Gd[e] = s;
        else d_Sd[e - NTILE * 16] = s;
    }
}

// ---- BN finalize via quadratic form ----
__global__ __launch_bounds__(64) void k_bnfin(const float* w2, const float* b2,
                                              const float* bnw, const float* bnb) {
    int c = blockIdx.x, j = threadIdx.x;
    __shared__ float w2s[64];
    __shared__ double sh1[64], sh2[64];
    w2s[j] = w2[c * 64 + j];
    __syncthreads();
    double wj = (double)w2s[j];
    double rowsum = 0.0;
    for (int k = 0; k < 64; k++) {
        int J = j >> 2, K = k >> 2, rj = j & 3, rk = k & 3;
        int off;
        if (J <= K) off = (J * 16 - (J * (J - 1)) / 2 + (K - J)) * 16 + rj * 4 + rk;
        else        off = (K * 16 - (K * (K - 1)) / 2 + (J - K)) * 16 + rk * 4 + rj;
        rowsum += d_Gd[off] * (double)w2s[k];
    }
    sh1[j] = wj * rowsum;
    sh2[j] = wj * d_Sd[j];
    __syncthreads();
    if (j == 0) {
        double quad = 0.0, ws = 0.0;
        for (int k = 0; k < 64; k++) { quad += sh1[k]; ws += sh2[k]; }
        double N   = (double)((long)NB * NPX);
        double b2c = (double)b2[c];
        double mu  = (ws + N * b2c) / N;
        double msq = (quad + 2.0 * b2c * ws + N * b2c * b2c) / N;
        double var = msq - mu * mu;
        float inv  = (float)(1.0 / sqrt(var + 1e-5));
        float A    = inv * bnw[c];
        d_bnA[c] = A;
        d_bnB[c] = bnb[c] - (float)mu * A;
    }
}

// ---- fused BN + softmax + gabor + A_tot: warp-per-pixel ----
__global__ __launch_bounds__(192) void k_atot() {
    int wid = threadIdx.x >> 5, lane = threadIdx.x & 31;
    int q = blockIdx.x * 6 + wid;
    int u = q / QW, v = q % QW;
    int px = u * HH + v;
    float2 Fv = make_float2(0.0f, 0.0f);
    if (lane < 12) {
        int b = lane / 3, i = lane % 3;
        int ip = (i == 0) ? 2 : (i - 1);
        Fv = d_F[b * 3 + ip][px];
    }
    float pv = (lane < 3) ? d_pix[lane][px] : 0.0f;
    float L   = __shfl_sync(0xffffffffu, pv, 0);
    float phi = __shfl_sync(0xffffffffu, pv, 1);
    float rr  = __shfl_sync(0xffffffffu, pv, 2);
    float Xr[4][3], Xi[4][3];
    #pragma unroll
    for (int b = 0; b < 4; b++)
        #pragma unroll
        for (int i = 0; i < 3; i++) {
            Xr[b][i] = __shfl_sync(0xffffffffu, Fv.x, b * 3 + i);
            Xi[b][i] = __shfl_sync(0xffffffffu, Fv.y, b * 3 + i);
        }
    float bnA[6], bnB[6];
    #pragma unroll
    for (int k = 0; k < 6; k++) {
        bnA[k] = d_bnA[lane + 32 * k];
        bnB[k] = d_bnB[lane + 32 * k];
    }
    float e[4][6], ssum[4];
    #pragma unroll
    for (int b = 0; b < 4; b++) {
        long base = ((long)b * NQ + q) * NCH + lane;
        float ls = 0.0f;
        #pragma unroll
        for (int k = 0; k < 6; k++) {
            e[b][k] = fexp(fmaf(d_h2q[base + 32 * k], bnA[k], bnB[k]));
            ls += e[b][k];
        }
        #pragma unroll
        for (int o = 16; o > 0; o >>= 1) ls += __shfl_xor_sync(0xffffffffu, ls, o);
        ssum[b] = ls;
    }
    float i0 = 1.0f / ssum[0], i1 = 1.0f / ssum[1], i2 = 1.0f / ssum[2], i3 = 1.0f / ssum[3];
    float accr = 0.0f, acci = 0.0f;
    #pragma unroll
    for (int k = 0; k < 6; k++) {
        int c = lane + 32 * k;
        float w0 = e[0][k] * i0, w1 = e[1][k] * i1, w2v = e[2][k] * i2, w3 = e[3][k] * i3;
        #pragma unroll
        for (int i = 0; i < 3; i++) {
            float ar = w0 * Xr[0][i] + w1 * Xr[1][i] + w2v * Xr[2][i] + w3 * Xr[3][i];
            float ai = w0 * Xi[0][i] + w1 * Xi[1][i] + w2v * Xi[2][i] + w3 * Xi[3][i];
            float4 pa = d_soiA[c * 3 + i];
            float2 pb = d_soiB[c * 3 + i];
            float dl = L - pa.x;
            float dp = phi - pa.z;
            float g = fexp(-(dl * dl) * pa.y - (dp * dp) * pa.w) * fcos(pb.x * rr) * pb.y;
            accr = fmaf(g, ar, accr);
            acci = fmaf(g, ai, acci);
        }
    }
    #pragma unroll
    for (int o = 16; o > 0; o >>= 1) {
        accr += __shfl_xor_sync(0xffffffffu, accr, o);
        acci += __shfl_xor_sync(0xffffffffu, acci, o);
    }
    if (lane == 0) d_A[q] = make_float2(accr, acci);
}

// ---- inverse DFT rows, quadrant-restricted, mask fused ----
__global__ __launch_bounds__(192) void k_inv_rows() {
    int o = blockIdx.x, u0 = blockIdx.y * 8, tid = threadIdx.x;
    int os = (o + 32) & 63;
    int lo0 = d_band[(os * 3 + 0) * 2] - 96, hi0 = d_band[(os * 3 + 0) * 2 + 1] - 96;
    int lo1 = d_band[(os * 3 + 1) * 2] - 96, hi1 = d_band[(os * 3 + 1) * 2 + 1] - 96;
    int lo2 = d_band[(os * 3 + 2) * 2] - 96, hi2 = d_band[(os * 3 + 2) * 2 + 1] - 96;
    __shared__ float2 qs[8][QW];
    for (int j = tid; j < 8 * QW; j += 192) {
        int r = j / QW, v = j % QW;
        int u = u0 + r;
        bool a0 = (u >= lo0) && (u < hi0), b0 = (v >= lo0) && (v < hi0);
        bool a1 = (u >= lo1) && (u < hi1), b1 = (v >= lo1) && (v < hi1);
        bool a2 = (u >= lo2) && (u < hi2), b2 = (v >= lo2) && (v < hi2);
        float m = (float)((a0 & b0) + (a1 & b1) + (a2 & b2));
        float2 a = d_A[u * QW + v];
        qs[r][v] = make_float2(a.x * m, a.y * m);
    }
    __syncthreads();
    float tr[8], ti[8];
    #pragma unroll
    for (int r = 0; r < 8; r++) { tr[r] = 0.0f; ti[r] = 0.0f; }
    #pragma unroll 8
    for (int v = 0; v < QW; v++) {
        float2 w = d_Wb[v * HH + tid];
        #pragma unroll
        for (int r = 0; r < 8; r++) {
            float2 qv = qs[r][v];
            tr[r] = fmaf(qv.x, w.x, fmaf(-qv.y, w.y, tr[r]));
            ti[r] = fmaf(qv.x, w.y, fmaf( qv.y, w.x, ti[r]));
        }
    }
    #pragma unroll
    for (int r = 0; r < 8; r++)
        d_T[o][(u0 + r) * HH + tid] = make_float2(tr[r], ti[r]);
}

// ---- inverse DFT cols (real part) ----
__global__ __launch_bounds__(192) void k_inv_cols() {
    int o = blockIdx.x, s0 = blockIdx.y * 8, tid = threadIdx.x;
    __shared__ float2 wt[8][QW];
    for (int j = tid; j < 8 * QW; j += 192) {
        int r = j / QW, u = j % QW;
        wt[r][u] = d_Wb[(s0 + r) * HH + u];
    }
    __syncthreads();
    float acc[8];
    #pragma unroll
    for (int r = 0; r < 8; r++) acc[r] = 0.0f;
    #pragma unroll 8
    for (int u = 0; u < QW; u++) {
        float2 t = d_T[o][u * HH + tid];
        #pragma unroll
        for (int r = 0; r < 8; r++) {
            float2 w = wt[r][u];
            acc[r] = fmaf(w.x, t.x, fmaf(-w.y, t.y, acc[r]));
        }
    }
    #pragma unroll
    for (int r = 0; r < 8; r++)
        d_xf[o * NPX + (s0 + r) * HH + tid] = acc[r];
}

// ---- 3x3 conv + mixing: padded float4 weights ----
__global__ __launch_bounds__(256) void k_conv(const float* x, const float* cw,
                                              const float* mp, float* out) {
    int b = blockIdx.z;
    int h0 = blockIdx.y * 16, w0 = blockIdx.x * 16;
    int tx = threadIdx.x, ty = threadIdx.y;
    int t = ty * 16 + tx;
    __shared__ float xt[3][18][18];
    __shared__ __align__(16) float cws[64 * 28];
    for (int j = t; j < 972; j += 256) {
        int i = j / 324, rem = j % 324, hh = rem / 18, ww = rem % 18;
        int gh = h0 - 1 + hh, gw = w0 - 1 + ww;
        xt[i][hh][ww] = (gh >= 0 && gh < HH && gw >= 0 && gw < HH)
                        ? x[(b * 3 + i) * NPX + gh * HH + gw] : 0.0f;
    }
    for (int j = t; j < 1728; j += 256) cws[(j / 27) * 28 + (j % 27)] = cw[j];
    for (int j = t; j < 64; j += 256) cws[j * 28 + 27] = 0.0f;
    __syncthreads();
    float mix = mp[0];
    float win[28];
    #pragma unroll
    for (int i = 0; i < 3; i++)
        #pragma unroll
        for (int kh = 0; kh < 3; kh++)
            #pragma unroll
            for (int kw = 0; kw < 3; kw++)
                win[i * 9 + kh * 3 + kw] = xt[i][ty + kh][tx + kw];
    win[27] = 0.0f;
    int pix = (h0 + ty) * HH + (w0 + tx);
    for (int o = 0; o < 64; o++) {
        float acc = 0.0f;
        #pragma unroll
        for (int g = 0; g < 7; g++) {
            float4 cv = *(const float4*)&cws[o * 28 + g * 4];
            acc = fmaf(win[g*4+0], cv.x, acc);
            acc = fmaf(win[g*4+1], cv.y, acc);
            acc = fmaf(win[g*4+2], cv.z, acc);
            acc = fmaf(win[g*4+3], cv.w, acc);
        }
        out[((b * 64 + o) * NPX) + pix] = fmaf(mix, d_xf[o * NPX + pix], (1.0f - mix) * acc);
    }
}

extern "C" void kernel_launch(void* const* d_in, const int* in_sizes, int n_in,
                              void* d_out, int out_size) {
    const float* x    = (const float*)d_in[0];
    const float* freq = (const float*)d_in[1];
    const float* thet = (const float*)d_in[2];
    const float* sigm = (const float*)d_in[3];
    const float* f0   = (const float*)d_in[4];
    const float* th0  = (const float*)d_in[5];
    const float* w1   = (const float*)d_in[6];
    const float* b1   = (const float*)d_in[7];
    const float* w2   = (const float*)d_in[8];
    const float* b2   = (const float*)d_in[9];
    const float* bnw  = (const float*)d_in[10];
    const float* bnb  = (const float*)d_in[11];
    const float* mp   = (const float*)d_in[12];
    const float* cw   = (const float*)d_in[13];
    const float* fbs  = (const float*)d_in[14];
    float* out = (float*)d_out;

    k_init<<<144, 256>>>(freq, thet, sigm, f0, th0, fbs);
    k_fwd_rows<<<dim3(12, 48), 192>>>(x);
    k_fwd_cols<<<dim3(12, 48), 192>>>();
    k_attn_stats<<<dim3(4, 288), 192>>>(w1, b1);
    k_attn_h2<<<dim3(4, 72), 192>>>(w1, b1, w2, b2);
    k_gred1<<<36, 256>>>();
    k_gred2<<<1, 256>>>();
    k_bnfin<<<192, 64>>>(w2, b2, bnw, bnb);
    k_atot<<<1536, 192>>>();
    k_inv_rows<<<dim3(64, 12), 192>>>();
    k_inv_cols<<<dim3(64, 24), 192>>>();
    k_conv<<<dim3(12, 12, 4), dim3(16, 16)>>>(x, cw, mp, out);
}